// round 12
// baseline (speedup 1.0000x reference)
#include <cuda_runtime.h>
#include <cuda_fp16.h>
#include <cstdint>
#include <cstddef>

// ---------------- problem constants ----------------
#define BATCH   8
#define IMG     384
#define CIN     3
#define PATCH   16
#define GRIDP   24
#define LTOK    576
#define WDIM    768
#define DEPTH   4
#define NHEAD   12
#define HDIM    64
#define MLPDIM  3072
#define NROWS   (BATCH*LTOK)
#define EPS     1e-6f
#define QKVN    (3*WDIM)            // 2304

// ---------------- PTX helpers ----------------
__device__ __forceinline__ uint32_t smem_to_u32(const void* smem_ptr) {
    uint32_t addr;
    asm("{ .reg .u64 tmp; cvta.to.shared.u64 tmp, %1; cvt.u32.u64 %0, tmp; }"
        : "=r"(addr) : "l"(smem_ptr));
    return addr;
}
#define CP_ASYNC16(dst, src) \
    asm volatile("cp.async.cg.shared.global [%0], [%1], 16;" :: "r"(dst), "l"(src) : "memory")
#define CP_COMMIT() asm volatile("cp.async.commit_group;" ::: "memory")
#define CP_WAIT2()  asm volatile("cp.async.wait_group 2;" ::: "memory")
#define CP_WAIT1()  asm volatile("cp.async.wait_group 1;" ::: "memory")

#define GDC_WAIT()   asm volatile("griddepcontrol.wait;" ::: "memory")
#define GDC_LAUNCH() asm volatile("griddepcontrol.launch_dependents;" ::: "memory")

#define LDSM_X4(r, addr) \
    asm volatile("ldmatrix.sync.aligned.m8n8.x4.shared.b16 {%0,%1,%2,%3}, [%4];" \
        : "=r"((r)[0]), "=r"((r)[1]), "=r"((r)[2]), "=r"((r)[3]) : "r"(addr))
#define LDSM_X4T(r, addr) \
    asm volatile("ldmatrix.sync.aligned.m8n8.x4.trans.shared.b16 {%0,%1,%2,%3}, [%4];" \
        : "=r"((r)[0]), "=r"((r)[1]), "=r"((r)[2]), "=r"((r)[3]) : "r"(addr))

#define MMA16816(d, a, b0, b1) \
    asm volatile("mma.sync.aligned.m16n8k16.row.col.f32.f16.f16.f32 " \
        "{%0,%1,%2,%3}, {%4,%5,%6,%7}, {%8,%9}, {%0,%1,%2,%3};" \
        : "+f"((d)[0]), "+f"((d)[1]), "+f"((d)[2]), "+f"((d)[3]) \
        : "r"((a)[0]), "r"((a)[1]), "r"((a)[2]), "r"((a)[3]), "r"(b0), "r"(b1))

#define SWZA(off) ((off) ^ (((off) >> 3) & 0x70))   // 128B rows
#define SWZB(off) ((off) ^ (((off) >> 4) & 0x70))   // 256B rows

// ---------------- scratch ----------------
__device__ __align__(256) float g_x   [NROWS*WDIM];
__device__ __align__(256) float g_y   [NROWS*WDIM];
__device__ __align__(256) float g_rope[4*LTOK*16];
__device__ __align__(256) float g_bqkv[DEPTH*QKVN];

__device__ __align__(256) __half g_yh [NROWS*WDIM];
__device__ __align__(256) __half g_oh [NROWS*WDIM];
__device__ __align__(256) __half g_qh [NROWS*WDIM];
__device__ __align__(256) __half g_kh [NROWS*WDIM];
__device__ __align__(256) __half g_vh [NROWS*WDIM];
__device__ __align__(256) __half g_h1h[NROWS*MLPDIM];

#define C0 589824
__device__ __align__(256) __half g_wh  [37*C0];      // [conv][wo x4][w1 x4][w2 x4]
__device__ __align__(256) __half g_wqkv[12*C0];      // [l][768][2304]

// ---------------- small helpers ----------------
__device__ __forceinline__ float gelu_f(float x) {
    float u = 0.7978845608028654f*(x + 0.044715f*x*x*x);
    float t = __expf(2.f*u);
    float th = 1.f - __fdividef(2.f, t + 1.f);
    return 0.5f*x*(1.f + th);
}

// ---------------- fused prep: wcvt | wqkvcvt | bcat | rope_cache ----------------
#define PREP_NB1 21312u   // 37*C0/4 items / 256
#define PREP_NB2 6912u    // 12*C0/4 items / 256
#define PREP_NB3 36u      // DEPTH*QKVN / 256
#define PREP_NB4 36u      // LTOK*16 / 256
__global__ void prep_k(const float* __restrict__ conv, const float* __restrict__ wo,
                       const float* __restrict__ w1, const float* __restrict__ w2,
                       const float* __restrict__ wq, const float* __restrict__ wk,
                       const float* __restrict__ wv,
                       const float* __restrict__ bq, const float* __restrict__ bk,
                       const float* __restrict__ bv,
                       __half* __restrict__ wdst, __half* __restrict__ wqkvdst,
                       float* __restrict__ bdst, float* __restrict__ cache) {
    uint32_t b = blockIdx.x;
    if (b < PREP_NB1) {
        size_t i4 = ((size_t)b*256 + threadIdx.x) * 4;
        if (i4 >= (size_t)37*C0) return;
        const float* src; size_t off;
        if      (i4 < (size_t)C0)    { src = conv; off = i4; }
        else if (i4 < (size_t)5*C0)  { src = wo;   off = i4 - (size_t)C0; }
        else if (i4 < (size_t)21*C0) { src = w1;   off = i4 - (size_t)5*C0; }
        else                         { src = w2;   off = i4 - (size_t)21*C0; }
        float4 v = *(const float4*)(src + off);
        __half2* d = (__half2*)(wdst + i4);
        d[0] = __floats2half2_rn(v.x, v.y);
        d[1] = __floats2half2_rn(v.z, v.w);
    } else if (b < PREP_NB1 + PREP_NB2) {
        size_t i4 = ((size_t)(b - PREP_NB1)*256 + threadIdx.x) * 4;
        if (i4 >= (size_t)12*C0) return;
        size_t l  = i4 / ((size_t)WDIM*QKVN);
        size_t r  = i4 % ((size_t)WDIM*QKVN);
        size_t k  = r / QKVN;
        size_t j  = r % QKVN;
        size_t blk = j / WDIM;
        const float* src = (blk == 0) ? wq : (blk == 1) ? wk : wv;
        float4 v = *(const float4*)(src + l*(size_t)C0 + k*WDIM + (j - blk*WDIM));
        __half2* d = (__half2*)(wqkvdst + i4);
        d[0] = __floats2half2_rn(v.x, v.y);
        d[1] = __floats2half2_rn(v.z, v.w);
    } else if (b < PREP_NB1 + PREP_NB2 + PREP_NB3) {
        int idx = (int)(b - PREP_NB1 - PREP_NB2)*256 + threadIdx.x;
        if (idx >= DEPTH*QKVN) return;
        int l = idx / QKVN, j = idx % QKVN;
        int blk = j / WDIM;
        const float* src = (blk == 0) ? bq : (blk == 1) ? bk : bv;
        bdst[idx] = src[l*WDIM + (j - blk*WDIM)];
    } else {
        int idx = (int)(b - PREP_NB1 - PREP_NB2 - PREP_NB3)*256 + threadIdx.x;
        if (idx >= LTOK*16) return;
        int f = idx % 16, l = idx / 16;
        float freq = (float)f / (15.f + 1e-9f);
        float inv  = powf(10000.f, -freq);
        float u = ((float)(l % GRIDP) + 0.5f) / (float)GRIDP;
        float v = ((float)(l / GRIDP) + 0.5f) / (float)GRIDP;
        float ax = u*inv, ay = v*inv;
        cache[0*LTOK*16 + idx] = cosf(ax);
        cache[1*LTOK*16 + idx] = sinf(ax);
        cache[2*LTOK*16 + idx] = cosf(ay);
        cache[3*LTOK*16 + idx] = sinf(ay);
    }
    GDC_LAUNCH();
}

// ---------------- im2col (fp16) ----------------
__global__ void im2col_k(const float* __restrict__ img, __half* __restrict__ oh) {
    int idx = blockIdx.x*256 + threadIdx.x;
    if (idx < NROWS*WDIM) {
        int t  = idx % WDIM;
        int nl = idx / WDIM;
        int l  = nl % LTOK;
        int n  = nl / LTOK;
        int ci = t % 3;
        int ij = t / 3;
        int j  = ij % PATCH;
        int i  = ij / PATCH;
        int px = l % GRIDP, py = l / GRIDP;
        float v = img[ (((size_t)n*IMG + (py*PATCH+i))*IMG + (px*PATCH+j))*CIN + ci ];
        oh[idx] = __float2half_rn(v);
    }
    GDC_LAUNCH();
}

// ---------------- layernorm: warp per row ----------------
__global__ void ln_k(const float* __restrict__ x, float* __restrict__ y,
                     __half* __restrict__ yh,
                     const float* __restrict__ sc, const float* __restrict__ bi) {
    GDC_WAIT();
    int wid = threadIdx.x >> 5, lane = threadIdx.x & 31;
    int row = blockIdx.x*8 + wid;
    const float4* xr = (const float4*)(x + (size_t)row*WDIM);
    float4 v[6];
    float s = 0.f, sq = 0.f;
    #pragma unroll
    for (int j = 0; j < 6; j++) {
        v[j] = xr[lane + j*32];
        s  += v[j].x + v[j].y + v[j].z + v[j].w;
        sq += v[j].x*v[j].x + v[j].y*v[j].y + v[j].z*v[j].z + v[j].w*v[j].w;
    }
    #pragma unroll
    for (int o = 16; o; o >>= 1) {
        s  += __shfl_xor_sync(0xffffffffu, s,  o);
        sq += __shfl_xor_sync(0xffffffffu, sq, o);
    }
    float m   = s * (1.f/(float)WDIM);
    float var = sq * (1.f/(float)WDIM) - m*m;
    float inv = rsqrtf(var + EPS);
    size_t base = (size_t)row*WDIM;
    #pragma unroll
    for (int j = 0; j < 6; j++) {
        int c = (lane + j*32)*4;
        float4 scv = *(const float4*)(sc + c);
        float4 biv = *(const float4*)(bi + c);
        float o0 = (v[j].x - m)*inv*scv.x + biv.x;
        float o1 = (v[j].y - m)*inv*scv.y + biv.y;
        float o2 = (v[j].z - m)*inv*scv.z + biv.z;
        float o3 = (v[j].w - m)*inv*scv.w + biv.w;
        if (y) *(float4*)(y + base + c) = make_float4(o0, o1, o2, o3);
        __half2 h0 = __floats2half2_rn(o0, o1);
        __half2 h1 = __floats2half2_rn(o2, o3);
        *(uint2*)(yh + base + c) = make_uint2(*(uint32_t*)&h0, *(uint32_t*)&h1);
    }
    GDC_LAUNCH();
}

// ---------------- GEMM core macros (tile 64x128, 128 thr, 3 stages) ----------------
// PDL: B (weights) for stages 0,1 issued BEFORE griddepcontrol.wait (independent
// of immediate predecessor); A (activations) issued after. Group structure:
// group0 = B0+B1+A0, group1 = A1, then one group per later stage -> CP_WAIT2
// before consuming stage s guarantees stage s complete (same counting as before).
#define GSTAGES 3
#define STAGE_BYTES 24576
#define GEMM_SMEM (GSTAGES*STAGE_BYTES)

#define GEMM_PREAMBLE \
    extern __shared__ __align__(1024) char smem[]; \
    const uint32_t sbase = smem_to_u32(smem); \
    int tid = threadIdx.x; \
    int wid = tid >> 5, lane = tid & 31; \
    int bn = blockIdx.x * 128, bm = blockIdx.y * 64; \
    const __half* Aptr = A + (size_t)bm*K; \
    const int nch = K >> 6; \
    auto issueA = [&](int ch, int stg) { \
        uint32_t sA = sbase + stg*STAGE_BYTES; \
        const __half* srcA = Aptr + ch*64; \
        _Pragma("unroll") \
        for (int rr = 0; rr < 4; rr++) { \
            int idx = rr*128 + tid; \
            int row = idx >> 3, u = idx & 7; \
            CP_ASYNC16(sA + SWZA((uint32_t)(row*128 + u*16)), srcA + (size_t)row*K + u*8); \
        } \
    }; \
    auto issueB = [&](int ch, int stg) { \
        uint32_t sB = sbase + stg*STAGE_BYTES + 8192; \
        const __half* srcB = B + (size_t)(ch*64)*N + bn; \
        _Pragma("unroll") \
        for (int rr = 0; rr < 8; rr++) { \
            int idx = rr*128 + tid; \
            int row = idx >> 4, u = idx & 15; \
            CP_ASYNC16(sB + SWZB((uint32_t)(row*256 + u*16)), srcB + (size_t)row*N + u*8); \
        } \
    }; \
    int m0w = (wid >> 1) * 32, n0w = (wid & 1) * 64; \
    int jj = lane >> 3, rr8 = lane & 7; \
    int arow = m0w + (jj & 1)*8 + rr8; \
    int acol = (jj >> 1) * 8; \
    int btrow = lane & 15; \
    int btcol = n0w + ((lane >> 4) << 3); \
    float acc[2][8][4]; \
    _Pragma("unroll") \
    for (int mt = 0; mt < 2; mt++) \
        _Pragma("unroll") \
        for (int nt = 0; nt < 8; nt++) \
            _Pragma("unroll") \
            for (int r = 0; r < 4; r++) acc[mt][nt][r] = 0.f; \
    issueB(0, 0); \
    issueB(1, 1); \
    GDC_WAIT(); \
    issueA(0, 0); CP_COMMIT(); \
    issueA(1, 1); CP_COMMIT(); \
    for (int ch = 0; ch < nch; ch++) { \
        if (ch + 2 < nch) { issueA(ch + 2, (ch + 2) % GSTAGES); issueB(ch + 2, (ch + 2) % GSTAGES); } \
        CP_COMMIT(); \
        CP_WAIT2(); \
        __syncthreads(); \
        uint32_t sA = sbase + (ch % GSTAGES)*STAGE_BYTES; \
        uint32_t sB = sA + 8192; \
        _Pragma("unroll") \
        for (int kk = 0; kk < 4; kk++) { \
            uint32_t a[2][4]; \
            _Pragma("unroll") \
            for (int mt = 0; mt < 2; mt++) { \
                uint32_t off = (uint32_t)((arow + mt*16)*128 + (kk*16 + acol)*2); \
                LDSM_X4(a[mt], sA + SWZA(off)); \
            } \
            uint32_t bt[4][4]; \
            _Pragma("unroll") \
            for (int np = 0; np < 4; np++) { \
                uint32_t off = (uint32_t)((kk*16 + btrow)*256 + (btcol + np*16)*2); \
                LDSM_X4T(bt[np], sB + SWZB(off)); \
            } \
            _Pragma("unroll") \
            for (int mt = 0; mt < 2; mt++) \
                _Pragma("unroll") \
                for (int nt = 0; nt < 8; nt++) \
                    MMA16816(acc[mt][nt], a[mt], bt[nt>>1][(nt&1)*2], bt[nt>>1][(nt&1)*2+1]); \
        } \
        __syncthreads(); \
    } \
    int lr = lane >> 2, lc = (lane & 3) * 2;

// ---------------- standard GEMM (fp32/fp16 out, residual, gelu) ----------------
template<bool GELU, bool RES, bool HOUT>
__global__ void __launch_bounds__(128, 3)
gemm_mma(const __half* __restrict__ A, const __half* __restrict__ B,
         const float* __restrict__ bias, const float* __restrict__ R,
         float* __restrict__ C, __half* __restrict__ Ch,
         int M, int N, int K) {
    GEMM_PREAMBLE
    #pragma unroll
    for (int mt = 0; mt < 2; mt++) {
        #pragma unroll
        for (int nt = 0; nt < 8; nt++) {
            int col = bn + n0w + nt*8 + lc;
            float b0 = bias[col], b1 = bias[col+1];
            int r0 = bm + m0w + mt*16 + lr;
            #pragma unroll
            for (int half = 0; half < 2; half++) {
                int m = r0 + half*8;
                float v0 = acc[mt][nt][half*2]   + b0;
                float v1 = acc[mt][nt][half*2+1] + b1;
                if (GELU) { v0 = gelu_f(v0); v1 = gelu_f(v1); }
                size_t o = (size_t)m*N + col;
                if (HOUT) {
                    *(__half2*)(Ch + o) = __floats2half2_rn(v0, v1);
                } else {
                    if (RES) {
                        float2 rv = *(const float2*)(R + o);
                        v0 += rv.x; v1 += rv.y;
                    }
                    *(float2*)(C + o) = make_float2(v0, v1);
                }
            }
        }
    }
    GDC_LAUNCH();
}

// ---------------- QKV GEMM: rope + head-major fp16 epilogue ----------------
__global__ void __launch_bounds__(128, 3)
gemm_qkv(const __half* __restrict__ A, const __half* __restrict__ B,
         const float* __restrict__ bias, const float* __restrict__ cache,
         __half* __restrict__ Qh, __half* __restrict__ Kh, __half* __restrict__ Vh,
         int M, int N, int K) {
    GEMM_PREAMBLE
    #pragma unroll
    for (int mt = 0; mt < 2; mt++) {
        #pragma unroll
        for (int nt = 0; nt < 8; nt++) {
            int colg = bn + n0w + nt*8 + lc;
            float b0 = bias[colg], b1 = bias[colg+1];
            int plane = colg / WDIM;
            int rem   = colg - plane*WDIM;
            int hh = rem >> 6;
            int d  = rem & 63;          // even
            int p  = d >> 1;
            int r0 = bm + m0w + mt*16 + lr;
            #pragma unroll
            for (int half = 0; half < 2; half++) {
                int m = r0 + half*8;
                int n = m / LTOK, l = m - n*LTOK;
                float v0 = acc[mt][nt][half*2]   + b0;
                float v1 = acc[mt][nt][half*2+1] + b1;
                size_t dsto = ((size_t)(n*NHEAD + hh)*LTOK + l)*HDIM + d;
                if (plane == 2) {
                    *(__half2*)(Vh + dsto) = __floats2half2_rn(v0, v1);
                } else {
                    float c, s;
                    if (p < 16) { c = cache[l*16 + p];             s = cache[LTOK*16 + l*16 + p]; }
                    else        { c = cache[2*LTOK*16 + l*16 + p-16]; s = cache[3*LTOK*16 + l*16 + p-16]; }
                    float rx = v0*c - v1*s;
                    float ry = v0*s + v1*c;
                    if (plane == 0) {
                        rx *= 0.125f; ry *= 0.125f;
                        *(__half2*)(Qh + dsto) = __floats2half2_rn(rx, ry);
                    } else {
                        *(__half2*)(Kh + dsto) = __floats2half2_rn(rx, ry);
                    }
                }
            }
        }
    }
    GDC_LAUNCH();
}

// ---------------- single-pass flash attention ----------------
#define FA_SQ   0
#define FA_K0   8192
#define FA_V0   16384
#define FA_K1   24576
#define FA_V1   32768
#define FA_SMEM 40960

__global__ void __launch_bounds__(128, 3)
fattn_k(const __half* __restrict__ Qh, const __half* __restrict__ Kh,
        const __half* __restrict__ Vh, __half* __restrict__ Oh) {
    extern __shared__ __align__(1024) char smem[];
    const uint32_t sb = smem_to_u32(smem);
    int tid = threadIdx.x;
    int w = tid >> 5, lane = tid & 31;
    int q0 = blockIdx.x * 64;
    int nh = blockIdx.y;
    int h  = nh % NHEAD, n = nh / NHEAD;

    const __half* qbase = Qh + ((size_t)nh*LTOK + q0)*HDIM;
    const __half* kbase = Kh + (size_t)nh*LTOK*HDIM;
    const __half* vbase = Vh + (size_t)nh*LTOK*HDIM;

    auto issue64 = [&](const __half* src, uint32_t dstoff) {
        #pragma unroll
        for (int it = 0; it < 4; it++) {
            int idx = it*128 + tid;
            int row = idx >> 3, u = idx & 7;
            CP_ASYNC16(sb + dstoff + SWZA((uint32_t)(row*128 + u*16)), src + row*HDIM + u*8);
        }
    };

    GDC_WAIT();     // Q/K/V all written by immediate predecessor (qkv gemm)

    issue64(qbase, FA_SQ);
    issue64(kbase, FA_K0);
    issue64(vbase, FA_V0);
    CP_COMMIT();
    issue64(kbase + 64*HDIM, FA_K1);
    issue64(vbase + 64*HDIM, FA_V1);
    CP_COMMIT();

    float m0 = -1e30f, m1 = -1e30f, l0 = 0.f, l1 = 0.f;
    float od[8][4];
    #pragma unroll
    for (int j = 0; j < 8; j++)
        #pragma unroll
        for (int r = 0; r < 4; r++) od[j][r] = 0.f;
    uint32_t qf[4][4];

    const int NCH = LTOK / 64;   // 9
    for (int c = 0; c < NCH; c++) {
        CP_WAIT1();
        __syncthreads();
        uint32_t kbuf = (c & 1) ? FA_K1 : FA_K0;
        uint32_t vbuf = (c & 1) ? FA_V1 : FA_V0;
        if (c == 0) {
            #pragma unroll
            for (int kk = 0; kk < 4; kk++) {
                uint32_t off = (uint32_t)((w*16 + (lane & 15))*128 + (kk*16 + ((lane>>4)<<3))*2);
                LDSM_X4(qf[kk], sb + FA_SQ + SWZA(off));
            }
        }
        float sf[8][4];
        #pragma unroll
        for (int j = 0; j < 8; j++)
            #pragma unroll
            for (int r = 0; r < 4; r++) sf[j][r] = 0.f;
        #pragma unroll
        for (int kk = 0; kk < 4; kk++) {
            #pragma unroll
            for (int kt = 0; kt < 4; kt++) {
                uint32_t bf[4];
                uint32_t off = (uint32_t)((kt*16 + (lane & 15))*128 + (kk*16 + ((lane>>4)<<3))*2);
                LDSM_X4(bf, sb + kbuf + SWZA(off));
                MMA16816(sf[2*kt],   qf[kk], bf[0], bf[2]);
                MMA16816(sf[2*kt+1], qf[kk], bf[1], bf[3]);
            }
        }
        float cm0 = -1e30f, cm1 = -1e30f;
        #pragma unroll
        for (int j = 0; j < 8; j++) {
            cm0 = fmaxf(cm0, fmaxf(sf[j][0], sf[j][1]));
            cm1 = fmaxf(cm1, fmaxf(sf[j][2], sf[j][3]));
        }
        cm0 = fmaxf(cm0, __shfl_xor_sync(0xffffffffu, cm0, 1));
        cm0 = fmaxf(cm0, __shfl_xor_sync(0xffffffffu, cm0, 2));
        cm1 = fmaxf(cm1, __shfl_xor_sync(0xffffffffu, cm1, 1));
        cm1 = fmaxf(cm1, __shfl_xor_sync(0xffffffffu, cm1, 2));
        float nm0 = fmaxf(m0, cm0), nm1 = fmaxf(m1, cm1);
        float sc0 = __expf(m0 - nm0), sc1 = __expf(m1 - nm1);
        m0 = nm0; m1 = nm1;
        float rs0 = 0.f, rs1 = 0.f;
        uint32_t pa[4][4];
        #pragma unroll
        for (int t = 0; t < 4; t++) {
            float e00 = __expf(sf[2*t][0]   - m0), e01 = __expf(sf[2*t][1]   - m0);
            float e10 = __expf(sf[2*t][2]   - m1), e11 = __expf(sf[2*t][3]   - m1);
            float e20 = __expf(sf[2*t+1][0] - m0), e21 = __expf(sf[2*t+1][1] - m0);
            float e30 = __expf(sf[2*t+1][2] - m1), e31 = __expf(sf[2*t+1][3] - m1);
            rs0 += e00 + e01 + e20 + e21;
            rs1 += e10 + e11 + e30 + e31;
            __half2 h;
            h = __floats2half2_rn(e00, e01); pa[t][0] = *(uint32_t*)&h;
            h = __floats2half2_rn(e10, e11); pa[t][1] = *(uint32_t*)&h;
            h = __floats2half2_rn(e20, e21); pa[t][2] = *(uint32_t*)&h;
            h = __floats2half2_rn(e30, e31); pa[t][3] = *(uint32_t*)&h;
        }
        rs0 += __shfl_xor_sync(0xffffffffu, rs0, 1);
        rs0 += __shfl_xor_sync(0xffffffffu, rs0, 2);
        rs1 += __shfl_xor_sync(0xffffffffu, rs1, 1);
        rs1 += __shfl_xor_sync(0xffffffffu, rs1, 2);
        l0 = l0*sc0 + rs0;
        l1 = l1*sc1 + rs1;
        #pragma unroll
        for (int j = 0; j < 8; j++) {
            od[j][0] *= sc0; od[j][1] *= sc0;
            od[j][2] *= sc1; od[j][3] *= sc1;
        }
        #pragma unroll
        for (int t = 0; t < 4; t++) {
            #pragma unroll
            for (int dt = 0; dt < 4; dt++) {
                uint32_t vb[4];
                uint32_t off = (uint32_t)((t*16 + (lane & 15))*128 + (dt*16 + ((lane>>4)<<3))*2);
                LDSM_X4T(vb, sb + vbuf + SWZA(off));
                MMA16816(od[2*dt],   pa[t], vb[0], vb[1]);
                MMA16816(od[2*dt+1], pa[t], vb[2], vb[3]);
            }
        }
        __syncthreads();
        if (c + 2 < NCH) {
            issue64(kbase + (c+2)*64*HDIM, (c & 1) ? FA_K1 : FA_K0);
            issue64(vbase + (c+2)*64*HDIM, (c & 1) ? FA_V1 : FA_V0);
        }
        CP_COMMIT();
    }

    float inv0 = 1.f / l0, inv1 = 1.f / l1;
    int row = lane >> 2;
    int gq0 = q0 + w*16 + row;
    #pragma unroll
    for (int j = 0; j < 8; j++) {
        int col = j*8 + (lane & 3)*2;
        *(__half2*)(Oh + ((size_t)(n*LTOK + gq0))*WDIM + h*HDIM + col) =
            __floats2half2_rn(od[j][0]*inv0, od[j][1]*inv0);
        *(__half2*)(Oh + ((size_t)(n*LTOK + gq0 + 8))*WDIM + h*HDIM + col) =
            __floats2half2_rn(od[j][2]*inv1, od[j][3]*inv1);
    }
    GDC_LAUNCH();
}

// ---------------- final mean ----------------
__global__ void mean_k(const float* __restrict__ y, float* __restrict__ out) {
    GDC_WAIT();
    int c = blockIdx.x*256 + threadIdx.x;
    int n = blockIdx.y;
    if (c < WDIM) {
        float acc = 0.f;
        for (int l = 0; l < LTOK; l++)
            acc += y[(size_t)(n*LTOK + l)*WDIM + c];
        out[(size_t)n*WDIM + c] = acc * (1.f/(float)LTOK);
    }
    GDC_LAUNCH();
}

// ---------------- PDL launch helper ----------------
template<class Kern, class... Args>
static inline void launch_pdl(Kern k, dim3 g, dim3 b, size_t sm, Args... args) {
    cudaLaunchConfig_t cfg = {};
    cfg.gridDim = g;
    cfg.blockDim = b;
    cfg.dynamicSmemBytes = sm;
    cudaLaunchAttribute at[1];
    at[0].id = cudaLaunchAttributeProgrammaticStreamSerialization;
    at[0].val.programmaticStreamSerializationAllowed = 1;
    cfg.attrs = at;
    cfg.numAttrs = 1;
    cudaLaunchKernelEx(&cfg, k, args...);
}

// ---------------- host orchestration ----------------
extern "C" void kernel_launch(void* const* d_in, const int* in_sizes, int n_in,
                              void* d_out, int out_size) {
    const float* image     = (const float*)d_in[0];
    const float* conv_ker  = (const float*)d_in[1];
    const float* conv_bias = (const float*)d_in[2];
    const float* ln1_scale = (const float*)d_in[3];
    const float* ln1_bias  = (const float*)d_in[4];
    const float* wq        = (const float*)d_in[5];
    const float* bq        = (const float*)d_in[6];
    const float* wk        = (const float*)d_in[7];
    const float* bk        = (const float*)d_in[8];
    const float* wv        = (const float*)d_in[9];
    const float* bv        = (const float*)d_in[10];
    const float* wo        = (const float*)d_in[11];
    const float* bo        = (const float*)d_in[12];
    const float* ln2_scale = (const float*)d_in[13];
    const float* ln2_bias  = (const float*)d_in[14];
    const float* w1        = (const float*)d_in[15];
    const float* b1        = (const float*)d_in[16];
    const float* w2        = (const float*)d_in[17];
    const float* b2        = (const float*)d_in[18];
    const float* lnf_scale = (const float*)d_in[19];
    const float* lnf_bias  = (const float*)d_in[20];
    float* out = (float*)d_out;

    float *x, *y, *rope, *bqkv;
    __half *yh, *oh, *qh, *kh, *vh, *h1h, *wh, *wqkvh;
    cudaGetSymbolAddress((void**)&x,    g_x);
    cudaGetSymbolAddress((void**)&y,    g_y);
    cudaGetSymbolAddress((void**)&rope, g_rope);
    cudaGetSymbolAddress((void**)&bqkv, g_bqkv);
    cudaGetSymbolAddress((void**)&yh,   g_yh);
    cudaGetSymbolAddress((void**)&oh,   g_oh);
    cudaGetSymbolAddress((void**)&qh,   g_qh);
    cudaGetSymbolAddress((void**)&kh,   g_kh);
    cudaGetSymbolAddress((void**)&vh,   g_vh);
    cudaGetSymbolAddress((void**)&h1h,  g_h1h);
    cudaGetSymbolAddress((void**)&wh,   g_wh);
    cudaGetSymbolAddress((void**)&wqkvh,g_wqkv);

    cudaFuncSetAttribute(gemm_mma<false,false,false>, cudaFuncAttributeMaxDynamicSharedMemorySize, GEMM_SMEM);
    cudaFuncSetAttribute(gemm_mma<false,true, false>, cudaFuncAttributeMaxDynamicSharedMemorySize, GEMM_SMEM);
    cudaFuncSetAttribute(gemm_mma<true, false,true >, cudaFuncAttributeMaxDynamicSharedMemorySize, GEMM_SMEM);
    cudaFuncSetAttribute(gemm_qkv, cudaFuncAttributeMaxDynamicSharedMemorySize, GEMM_SMEM);
    cudaFuncSetAttribute(fattn_k,  cudaFuncAttributeMaxDynamicSharedMemorySize, FA_SMEM);

    __half* w_conv = wh;
    __half* w_o    = wh + (size_t)1*C0;
    __half* w_1    = wh + (size_t)5*C0;
    __half* w_2    = wh + (size_t)21*C0;

    // fused prep (one launch)
    launch_pdl(prep_k, dim3(PREP_NB1 + PREP_NB2 + PREP_NB3 + PREP_NB4), dim3(256), 0,
               conv_ker, wo, w1, w2, wq, wk, wv, bq, bk, bv, wh, wqkvh, bqkv, rope);

    launch_pdl(im2col_k, dim3((NROWS*WDIM + 255)/256), dim3(256), 0, image, h1h);
    launch_pdl(gemm_mma<false,false,false>, dim3(WDIM/128, NROWS/64), dim3(128), (size_t)GEMM_SMEM,
               (const __half*)h1h, (const __half*)w_conv, conv_bias,
               (const float*)nullptr, x, (__half*)nullptr, NROWS, WDIM, WDIM);

    dim3 gProj(WDIM/128,  NROWS/64);   // 6 x 72
    dim3 gQkv (QKVN/128,  NROWS/64);   // 18 x 72
    dim3 gMlp1(MLPDIM/128,NROWS/64);   // 24 x 72
    dim3 gAttn(LTOK/64, BATCH*NHEAD);  // 9 x 96
    dim3 gLn(NROWS/8);

    for (int l = 0; l < DEPTH; l++) {
        const __half* wqkv_l = wqkvh + (size_t)l*3*C0;
        const __half* wo_l   = w_o + (size_t)l*C0;
        const __half* w1_l   = w_1 + (size_t)l*4*C0;
        const __half* w2_l   = w_2 + (size_t)l*4*C0;
        const float* bqkv_l = bqkv + (size_t)l*QKVN;
        const float* bo_l = bo + (size_t)l*WDIM;
        const float* b1_l = b1 + (size_t)l*MLPDIM;
        const float* b2_l = b2 + (size_t)l*WDIM;

        launch_pdl(ln_k, gLn, dim3(256), 0, (const float*)x, (float*)nullptr, yh,
                   ln1_scale + (size_t)l*WDIM, ln1_bias + (size_t)l*WDIM);

        launch_pdl(gemm_qkv, gQkv, dim3(128), (size_t)GEMM_SMEM,
                   (const __half*)yh, wqkv_l, bqkv_l, (const float*)rope,
                   qh, kh, vh, NROWS, QKVN, WDIM);

        launch_pdl(fattn_k, gAttn, dim3(128), (size_t)FA_SMEM,
                   (const __half*)qh, (const __half*)kh, (const __half*)vh, oh);

        launch_pdl(gemm_mma<false,true,false>, gProj, dim3(128), (size_t)GEMM_SMEM,
                   (const __half*)oh, wo_l, bo_l, (const float*)x, x, (__half*)nullptr,
                   NROWS, WDIM, WDIM);

        launch_pdl(ln_k, gLn, dim3(256), 0, (const float*)x, (float*)nullptr, yh,
                   ln2_scale + (size_t)l*WDIM, ln2_bias + (size_t)l*WDIM);

        launch_pdl(gemm_mma<true,false,true>, gMlp1, dim3(128), (size_t)GEMM_SMEM,
                   (const __half*)yh, w1_l, b1_l, (const float*)nullptr,
                   (float*)nullptr, h1h, NROWS, MLPDIM, WDIM);
        launch_pdl(gemm_mma<false,true,false>, gProj, dim3(128), (size_t)GEMM_SMEM,
                   (const __half*)h1h, w2_l, b2_l, (const float*)x, x, (__half*)nullptr,
                   NROWS, WDIM, MLPDIM);
    }

    launch_pdl(ln_k, gLn, dim3(256), 0, (const float*)x, y, yh, lnf_scale, lnf_bias);
    launch_pdl(mean_k, dim3((WDIM + 255)/256, BATCH), dim3(256), 0, (const float*)y, out);
}

// round 13
// speedup vs baseline: 1.0418x; 1.0418x over previous
#include <cuda_runtime.h>
#include <cuda_fp16.h>
#include <cstdint>
#include <cstddef>

// ---------------- problem constants ----------------
#define BATCH   8
#define IMG     384
#define CIN     3
#define PATCH   16
#define GRIDP   24
#define LTOK    576
#define WDIM    768
#define DEPTH   4
#define NHEAD   12
#define HDIM    64
#define MLPDIM  3072
#define NROWS   (BATCH*LTOK)
#define EPS     1e-6f
#define QKVN    (3*WDIM)            // 2304

// ---------------- PTX helpers ----------------
__device__ __forceinline__ uint32_t smem_to_u32(const void* smem_ptr) {
    uint32_t addr;
    asm("{ .reg .u64 tmp; cvta.to.shared.u64 tmp, %1; cvt.u32.u64 %0, tmp; }"
        : "=r"(addr) : "l"(smem_ptr));
    return addr;
}
#define CP_ASYNC16(dst, src) \
    asm volatile("cp.async.cg.shared.global [%0], [%1], 16;" :: "r"(dst), "l"(src) : "memory")
#define CP_COMMIT() asm volatile("cp.async.commit_group;" ::: "memory")
#define CP_WAIT1()  asm volatile("cp.async.wait_group 1;" ::: "memory")

#define LDSM_X4(r, addr) \
    asm volatile("ldmatrix.sync.aligned.m8n8.x4.shared.b16 {%0,%1,%2,%3}, [%4];" \
        : "=r"((r)[0]), "=r"((r)[1]), "=r"((r)[2]), "=r"((r)[3]) : "r"(addr))
#define LDSM_X4T(r, addr) \
    asm volatile("ldmatrix.sync.aligned.m8n8.x4.trans.shared.b16 {%0,%1,%2,%3}, [%4];" \
        : "=r"((r)[0]), "=r"((r)[1]), "=r"((r)[2]), "=r"((r)[3]) : "r"(addr))

#define MMA16816(d, a, b0, b1) \
    asm volatile("mma.sync.aligned.m16n8k16.row.col.f32.f16.f16.f32 " \
        "{%0,%1,%2,%3}, {%4,%5,%6,%7}, {%8,%9}, {%0,%1,%2,%3};" \
        : "+f"((d)[0]), "+f"((d)[1]), "+f"((d)[2]), "+f"((d)[3]) \
        : "r"((a)[0]), "r"((a)[1]), "r"((a)[2]), "r"((a)[3]), "r"(b0), "r"(b1))

#define SWZA(off) ((off) ^ (((off) >> 3) & 0x70))   // 128B rows
#define SWZB(off) ((off) ^ (((off) >> 4) & 0x70))   // 256B rows

// ---------------- scratch ----------------
__device__ __align__(256) float g_x   [NROWS*WDIM];
__device__ __align__(256) float g_y   [NROWS*WDIM];
__device__ __align__(256) float g_rope[4*LTOK*16];
__device__ __align__(256) float g_bqkv[DEPTH*QKVN];

__device__ __align__(256) __half g_yh [NROWS*WDIM];
__device__ __align__(256) __half g_oh [NROWS*WDIM];
__device__ __align__(256) __half g_qh [NROWS*WDIM];
__device__ __align__(256) __half g_kh [NROWS*WDIM];
__device__ __align__(256) __half g_vh [NROWS*WDIM];
__device__ __align__(256) __half g_h1h[NROWS*MLPDIM];

#define C0 589824
__device__ __align__(256) __half g_wh  [37*C0];      // [conv][wo x4][w1 x4][w2 x4]
__device__ __align__(256) __half g_wqkv[12*C0];      // [l][768][2304]

// ---------------- small helpers ----------------
__device__ __forceinline__ float gelu_f(float x) {
    float u = 0.7978845608028654f*(x + 0.044715f*x*x*x);
    float t = __expf(2.f*u);
    float th = 1.f - __fdividef(2.f, t + 1.f);
    return 0.5f*x*(1.f + th);
}

// ---------------- fused prep: wcvt | wqkvcvt | bcat | rope_cache ----------------
#define PREP_NB1 21312u   // 37*C0/4 items / 256
#define PREP_NB2 6912u    // 12*C0/4 items / 256
#define PREP_NB3 36u      // DEPTH*QKVN / 256
#define PREP_NB4 36u      // LTOK*16 / 256
__global__ void prep_k(const float* __restrict__ conv, const float* __restrict__ wo,
                       const float* __restrict__ w1, const float* __restrict__ w2,
                       const float* __restrict__ wq, const float* __restrict__ wk,
                       const float* __restrict__ wv,
                       const float* __restrict__ bq, const float* __restrict__ bk,
                       const float* __restrict__ bv,
                       __half* __restrict__ wdst, __half* __restrict__ wqkvdst,
                       float* __restrict__ bdst, float* __restrict__ cache) {
    uint32_t b = blockIdx.x;
    if (b < PREP_NB1) {
        size_t i4 = ((size_t)b*256 + threadIdx.x) * 4;
        if (i4 >= (size_t)37*C0) return;
        const float* src; size_t off;
        if      (i4 < (size_t)C0)    { src = conv; off = i4; }
        else if (i4 < (size_t)5*C0)  { src = wo;   off = i4 - (size_t)C0; }
        else if (i4 < (size_t)21*C0) { src = w1;   off = i4 - (size_t)5*C0; }
        else                         { src = w2;   off = i4 - (size_t)21*C0; }
        float4 v = *(const float4*)(src + off);
        __half2* d = (__half2*)(wdst + i4);
        d[0] = __floats2half2_rn(v.x, v.y);
        d[1] = __floats2half2_rn(v.z, v.w);
    } else if (b < PREP_NB1 + PREP_NB2) {
        size_t i4 = ((size_t)(b - PREP_NB1)*256 + threadIdx.x) * 4;
        if (i4 >= (size_t)12*C0) return;
        size_t l  = i4 / ((size_t)WDIM*QKVN);
        size_t r  = i4 % ((size_t)WDIM*QKVN);
        size_t k  = r / QKVN;
        size_t j  = r % QKVN;
        size_t blk = j / WDIM;
        const float* src = (blk == 0) ? wq : (blk == 1) ? wk : wv;
        float4 v = *(const float4*)(src + l*(size_t)C0 + k*WDIM + (j - blk*WDIM));
        __half2* d = (__half2*)(wqkvdst + i4);
        d[0] = __floats2half2_rn(v.x, v.y);
        d[1] = __floats2half2_rn(v.z, v.w);
    } else if (b < PREP_NB1 + PREP_NB2 + PREP_NB3) {
        int idx = (int)(b - PREP_NB1 - PREP_NB2)*256 + threadIdx.x;
        if (idx >= DEPTH*QKVN) return;
        int l = idx / QKVN, j = idx % QKVN;
        int blk = j / WDIM;
        const float* src = (blk == 0) ? bq : (blk == 1) ? bk : bv;
        bdst[idx] = src[l*WDIM + (j - blk*WDIM)];
    } else {
        int idx = (int)(b - PREP_NB1 - PREP_NB2 - PREP_NB3)*256 + threadIdx.x;
        if (idx >= LTOK*16) return;
        int f = idx % 16, l = idx / 16;
        float freq = (float)f / (15.f + 1e-9f);
        float inv  = powf(10000.f, -freq);
        float u = ((float)(l % GRIDP) + 0.5f) / (float)GRIDP;
        float v = ((float)(l / GRIDP) + 0.5f) / (float)GRIDP;
        float ax = u*inv, ay = v*inv;
        cache[0*LTOK*16 + idx] = cosf(ax);
        cache[1*LTOK*16 + idx] = sinf(ax);
        cache[2*LTOK*16 + idx] = cosf(ay);
        cache[3*LTOK*16 + idx] = sinf(ay);
    }
}

// ---------------- im2col (fp16) ----------------
__global__ void im2col_k(const float* __restrict__ img, __half* __restrict__ oh) {
    int idx = blockIdx.x*256 + threadIdx.x;
    if (idx >= NROWS*WDIM) return;
    int t  = idx % WDIM;
    int nl = idx / WDIM;
    int l  = nl % LTOK;
    int n  = nl / LTOK;
    int ci = t % 3;
    int ij = t / 3;
    int j  = ij % PATCH;
    int i  = ij / PATCH;
    int px = l % GRIDP, py = l / GRIDP;
    float v = img[ (((size_t)n*IMG + (py*PATCH+i))*IMG + (px*PATCH+j))*CIN + ci ];
    oh[idx] = __float2half_rn(v);
}

// ---------------- layernorm: warp per row ----------------
__global__ void ln_k(const float* __restrict__ x, float* __restrict__ y,
                     __half* __restrict__ yh,
                     const float* __restrict__ sc, const float* __restrict__ bi) {
    int wid = threadIdx.x >> 5, lane = threadIdx.x & 31;
    int row = blockIdx.x*8 + wid;
    const float4* xr = (const float4*)(x + (size_t)row*WDIM);
    float4 v[6];
    float s = 0.f, sq = 0.f;
    #pragma unroll
    for (int j = 0; j < 6; j++) {
        v[j] = xr[lane + j*32];
        s  += v[j].x + v[j].y + v[j].z + v[j].w;
        sq += v[j].x*v[j].x + v[j].y*v[j].y + v[j].z*v[j].z + v[j].w*v[j].w;
    }
    #pragma unroll
    for (int o = 16; o; o >>= 1) {
        s  += __shfl_xor_sync(0xffffffffu, s,  o);
        sq += __shfl_xor_sync(0xffffffffu, sq, o);
    }
    float m   = s * (1.f/(float)WDIM);
    float var = sq * (1.f/(float)WDIM) - m*m;
    float inv = rsqrtf(var + EPS);
    size_t base = (size_t)row*WDIM;
    #pragma unroll
    for (int j = 0; j < 6; j++) {
        int c = (lane + j*32)*4;
        float4 scv = *(const float4*)(sc + c);
        float4 biv = *(const float4*)(bi + c);
        float o0 = (v[j].x - m)*inv*scv.x + biv.x;
        float o1 = (v[j].y - m)*inv*scv.y + biv.y;
        float o2 = (v[j].z - m)*inv*scv.z + biv.z;
        float o3 = (v[j].w - m)*inv*scv.w + biv.w;
        if (y) *(float4*)(y + base + c) = make_float4(o0, o1, o2, o3);
        __half2 h0 = __floats2half2_rn(o0, o1);
        __half2 h1 = __floats2half2_rn(o2, o3);
        *(uint2*)(yh + base + c) = make_uint2(*(uint32_t*)&h0, *(uint32_t*)&h1);
    }
}

// ---------------- GEMM core (tile 64x128, 128 thr, 3 stages, ONE barrier/chunk) ----------------
// Order per chunk: WAIT1 -> sync -> issue(ch+2) -> commit -> compute(ch).
// Safety: stage (ch+2)%3 last read in iter ch-1, finished before this barrier;
// wait_group 1 completes group g(ch) (= stage ch) since commits are 1/iter + 2 prologue.
#define GSTAGES 3
#define STAGE_BYTES 24576
#define GEMM_SMEM (GSTAGES*STAGE_BYTES)

#define GEMM_PREAMBLE \
    extern __shared__ __align__(1024) char smem[]; \
    const uint32_t sbase = smem_to_u32(smem); \
    int tid = threadIdx.x; \
    int wid = tid >> 5, lane = tid & 31; \
    int bn = blockIdx.x * 128, bm = blockIdx.y * 64; \
    const __half* Aptr = A + (size_t)bm*K; \
    const int nch = K >> 6; \
    auto issue = [&](int ch, int stg) { \
        uint32_t sA = sbase + stg*STAGE_BYTES; \
        uint32_t sB = sA + 8192; \
        const __half* srcA = Aptr + ch*64; \
        _Pragma("unroll") \
        for (int rr = 0; rr < 4; rr++) { \
            int idx = rr*128 + tid; \
            int row = idx >> 3, u = idx & 7; \
            CP_ASYNC16(sA + SWZA((uint32_t)(row*128 + u*16)), srcA + (size_t)row*K + u*8); \
        } \
        const __half* srcB = B + (size_t)(ch*64)*N + bn; \
        _Pragma("unroll") \
        for (int rr = 0; rr < 8; rr++) { \
            int idx = rr*128 + tid; \
            int row = idx >> 4, u = idx & 15; \
            CP_ASYNC16(sB + SWZB((uint32_t)(row*256 + u*16)), srcB + (size_t)row*N + u*8); \
        } \
    }; \
    int m0w = (wid >> 1) * 32, n0w = (wid & 1) * 64; \
    int jj = lane >> 3, rr8 = lane & 7; \
    int arow = m0w + (jj & 1)*8 + rr8; \
    int acol = (jj >> 1) * 8; \
    int btrow = lane & 15; \
    int btcol = n0w + ((lane >> 4) << 3); \
    float acc[2][8][4]; \
    _Pragma("unroll") \
    for (int mt = 0; mt < 2; mt++) \
        _Pragma("unroll") \
        for (int nt = 0; nt < 8; nt++) \
            _Pragma("unroll") \
            for (int r = 0; r < 4; r++) acc[mt][nt][r] = 0.f; \
    issue(0, 0); CP_COMMIT(); \
    issue(1, 1); CP_COMMIT(); \
    for (int ch = 0; ch < nch; ch++) { \
        CP_WAIT1(); \
        __syncthreads(); \
        if (ch + 2 < nch) issue(ch + 2, (ch + 2) % GSTAGES); \
        CP_COMMIT(); \
        uint32_t sA = sbase + (ch % GSTAGES)*STAGE_BYTES; \
        uint32_t sB = sA + 8192; \
        _Pragma("unroll") \
        for (int kk = 0; kk < 4; kk++) { \
            uint32_t a[2][4]; \
            _Pragma("unroll") \
            for (int mt = 0; mt < 2; mt++) { \
                uint32_t off = (uint32_t)((arow + mt*16)*128 + (kk*16 + acol)*2); \
                LDSM_X4(a[mt], sA + SWZA(off)); \
            } \
            uint32_t bt[4][4]; \
            _Pragma("unroll") \
            for (int np = 0; np < 4; np++) { \
                uint32_t off = (uint32_t)((kk*16 + btrow)*256 + (btcol + np*16)*2); \
                LDSM_X4T(bt[np], sB + SWZB(off)); \
            } \
            _Pragma("unroll") \
            for (int mt = 0; mt < 2; mt++) \
                _Pragma("unroll") \
                for (int nt = 0; nt < 8; nt++) \
                    MMA16816(acc[mt][nt], a[mt], bt[nt>>1][(nt&1)*2], bt[nt>>1][(nt&1)*2+1]); \
        } \
    } \
    int lr = lane >> 2, lc = (lane & 3) * 2;

// ---------------- standard GEMM (fp32/fp16 out, residual, gelu) ----------------
template<bool GELU, bool RES, bool HOUT>
__global__ void __launch_bounds__(128, 3)
gemm_mma(const __half* __restrict__ A, const __half* __restrict__ B,
         const float* __restrict__ bias, const float* __restrict__ R,
         float* __restrict__ C, __half* __restrict__ Ch,
         int M, int N, int K) {
    GEMM_PREAMBLE
    #pragma unroll
    for (int mt = 0; mt < 2; mt++) {
        #pragma unroll
        for (int nt = 0; nt < 8; nt++) {
            int col = bn + n0w + nt*8 + lc;
            float b0 = bias[col], b1 = bias[col+1];
            int r0 = bm + m0w + mt*16 + lr;
            #pragma unroll
            for (int half = 0; half < 2; half++) {
                int m = r0 + half*8;
                float v0 = acc[mt][nt][half*2]   + b0;
                float v1 = acc[mt][nt][half*2+1] + b1;
                if (GELU) { v0 = gelu_f(v0); v1 = gelu_f(v1); }
                size_t o = (size_t)m*N + col;
                if (HOUT) {
                    *(__half2*)(Ch + o) = __floats2half2_rn(v0, v1);
                } else {
                    if (RES) {
                        float2 rv = *(const float2*)(R + o);
                        v0 += rv.x; v1 += rv.y;
                    }
                    *(float2*)(C + o) = make_float2(v0, v1);
                }
            }
        }
    }
}

// ---------------- QKV GEMM: rope + head-major fp16 epilogue ----------------
__global__ void __launch_bounds__(128, 3)
gemm_qkv(const __half* __restrict__ A, const __half* __restrict__ B,
         const float* __restrict__ bias, const float* __restrict__ cache,
         __half* __restrict__ Qh, __half* __restrict__ Kh, __half* __restrict__ Vh,
         int M, int N, int K) {
    GEMM_PREAMBLE
    #pragma unroll
    for (int mt = 0; mt < 2; mt++) {
        #pragma unroll
        for (int nt = 0; nt < 8; nt++) {
            int colg = bn + n0w + nt*8 + lc;
            float b0 = bias[colg], b1 = bias[colg+1];
            int plane = colg / WDIM;
            int rem   = colg - plane*WDIM;
            int hh = rem >> 6;
            int d  = rem & 63;          // even
            int p  = d >> 1;
            int r0 = bm + m0w + mt*16 + lr;
            #pragma unroll
            for (int half = 0; half < 2; half++) {
                int m = r0 + half*8;
                int n = m / LTOK, l = m - n*LTOK;
                float v0 = acc[mt][nt][half*2]   + b0;
                float v1 = acc[mt][nt][half*2+1] + b1;
                size_t dsto = ((size_t)(n*NHEAD + hh)*LTOK + l)*HDIM + d;
                if (plane == 2) {
                    *(__half2*)(Vh + dsto) = __floats2half2_rn(v0, v1);
                } else {
                    float c, s;
                    if (p < 16) { c = cache[l*16 + p];             s = cache[LTOK*16 + l*16 + p]; }
                    else        { c = cache[2*LTOK*16 + l*16 + p-16]; s = cache[3*LTOK*16 + l*16 + p-16]; }
                    float rx = v0*c - v1*s;
                    float ry = v0*s + v1*c;
                    if (plane == 0) {
                        rx *= 0.125f; ry *= 0.125f;
                        *(__half2*)(Qh + dsto) = __floats2half2_rn(rx, ry);
                    } else {
                        *(__half2*)(Kh + dsto) = __floats2half2_rn(rx, ry);
                    }
                }
            }
        }
    }
}

// ---------------- single-pass flash attention (R9-proven) ----------------
#define FA_SQ   0
#define FA_K0   8192
#define FA_V0   16384
#define FA_K1   24576
#define FA_V1   32768
#define FA_SMEM 40960

__global__ void __launch_bounds__(128, 3)
fattn_k(const __half* __restrict__ Qh, const __half* __restrict__ Kh,
        const __half* __restrict__ Vh, __half* __restrict__ Oh) {
    extern __shared__ __align__(1024) char smem[];
    const uint32_t sb = smem_to_u32(smem);
    int tid = threadIdx.x;
    int w = tid >> 5, lane = tid & 31;
    int q0 = blockIdx.x * 64;
    int nh = blockIdx.y;
    int h  = nh % NHEAD, n = nh / NHEAD;

    const __half* qbase = Qh + ((size_t)nh*LTOK + q0)*HDIM;
    const __half* kbase = Kh + (size_t)nh*LTOK*HDIM;
    const __half* vbase = Vh + (size_t)nh*LTOK*HDIM;

    auto issue64 = [&](const __half* src, uint32_t dstoff) {
        #pragma unroll
        for (int it = 0; it < 4; it++) {
            int idx = it*128 + tid;
            int row = idx >> 3, u = idx & 7;
            CP_ASYNC16(sb + dstoff + SWZA((uint32_t)(row*128 + u*16)), src + row*HDIM + u*8);
        }
    };

    issue64(qbase, FA_SQ);
    issue64(kbase, FA_K0);
    issue64(vbase, FA_V0);
    CP_COMMIT();
    issue64(kbase + 64*HDIM, FA_K1);
    issue64(vbase + 64*HDIM, FA_V1);
    CP_COMMIT();

    float m0 = -1e30f, m1 = -1e30f, l0 = 0.f, l1 = 0.f;
    float od[8][4];
    #pragma unroll
    for (int j = 0; j < 8; j++)
        #pragma unroll
        for (int r = 0; r < 4; r++) od[j][r] = 0.f;
    uint32_t qf[4][4];

    const int NCH = LTOK / 64;   // 9
    for (int c = 0; c < NCH; c++) {
        CP_WAIT1();
        __syncthreads();
        uint32_t kbuf = (c & 1) ? FA_K1 : FA_K0;
        uint32_t vbuf = (c & 1) ? FA_V1 : FA_V0;
        if (c == 0) {
            #pragma unroll
            for (int kk = 0; kk < 4; kk++) {
                uint32_t off = (uint32_t)((w*16 + (lane & 15))*128 + (kk*16 + ((lane>>4)<<3))*2);
                LDSM_X4(qf[kk], sb + FA_SQ + SWZA(off));
            }
        }
        float sf[8][4];
        #pragma unroll
        for (int j = 0; j < 8; j++)
            #pragma unroll
            for (int r = 0; r < 4; r++) sf[j][r] = 0.f;
        #pragma unroll
        for (int kk = 0; kk < 4; kk++) {
            #pragma unroll
            for (int kt = 0; kt < 4; kt++) {
                uint32_t bf[4];
                uint32_t off = (uint32_t)((kt*16 + (lane & 15))*128 + (kk*16 + ((lane>>4)<<3))*2);
                LDSM_X4(bf, sb + kbuf + SWZA(off));
                MMA16816(sf[2*kt],   qf[kk], bf[0], bf[2]);
                MMA16816(sf[2*kt+1], qf[kk], bf[1], bf[3]);
            }
        }
        float cm0 = -1e30f, cm1 = -1e30f;
        #pragma unroll
        for (int j = 0; j < 8; j++) {
            cm0 = fmaxf(cm0, fmaxf(sf[j][0], sf[j][1]));
            cm1 = fmaxf(cm1, fmaxf(sf[j][2], sf[j][3]));
        }
        cm0 = fmaxf(cm0, __shfl_xor_sync(0xffffffffu, cm0, 1));
        cm0 = fmaxf(cm0, __shfl_xor_sync(0xffffffffu, cm0, 2));
        cm1 = fmaxf(cm1, __shfl_xor_sync(0xffffffffu, cm1, 1));
        cm1 = fmaxf(cm1, __shfl_xor_sync(0xffffffffu, cm1, 2));
        float nm0 = fmaxf(m0, cm0), nm1 = fmaxf(m1, cm1);
        float sc0 = __expf(m0 - nm0), sc1 = __expf(m1 - nm1);
        m0 = nm0; m1 = nm1;
        float rs0 = 0.f, rs1 = 0.f;
        uint32_t pa[4][4];
        #pragma unroll
        for (int t = 0; t < 4; t++) {
            float e00 = __expf(sf[2*t][0]   - m0), e01 = __expf(sf[2*t][1]   - m0);
            float e10 = __expf(sf[2*t][2]   - m1), e11 = __expf(sf[2*t][3]   - m1);
            float e20 = __expf(sf[2*t+1][0] - m0), e21 = __expf(sf[2*t+1][1] - m0);
            float e30 = __expf(sf[2*t+1][2] - m1), e31 = __expf(sf[2*t+1][3] - m1);
            rs0 += e00 + e01 + e20 + e21;
            rs1 += e10 + e11 + e30 + e31;
            __half2 h;
            h = __floats2half2_rn(e00, e01); pa[t][0] = *(uint32_t*)&h;
            h = __floats2half2_rn(e10, e11); pa[t][1] = *(uint32_t*)&h;
            h = __floats2half2_rn(e20, e21); pa[t][2] = *(uint32_t*)&h;
            h = __floats2half2_rn(e30, e31); pa[t][3] = *(uint32_t*)&h;
        }
        rs0 += __shfl_xor_sync(0xffffffffu, rs0, 1);
        rs0 += __shfl_xor_sync(0xffffffffu, rs0, 2);
        rs1 += __shfl_xor_sync(0xffffffffu, rs1, 1);
        rs1 += __shfl_xor_sync(0xffffffffu, rs1, 2);
        l0 = l0*sc0 + rs0;
        l1 = l1*sc1 + rs1;
        #pragma unroll
        for (int j = 0; j < 8; j++) {
            od[j][0] *= sc0; od[j][1] *= sc0;
            od[j][2] *= sc1; od[j][3] *= sc1;
        }
        #pragma unroll
        for (int t = 0; t < 4; t++) {
            #pragma unroll
            for (int dt = 0; dt < 4; dt++) {
                uint32_t vb[4];
                uint32_t off = (uint32_t)((t*16 + (lane & 15))*128 + (dt*16 + ((lane>>4)<<3))*2);
                LDSM_X4T(vb, sb + vbuf + SWZA(off));
                MMA16816(od[2*dt],   pa[t], vb[0], vb[1]);
                MMA16816(od[2*dt+1], pa[t], vb[2], vb[3]);
            }
        }
        __syncthreads();
        if (c + 2 < NCH) {
            issue64(kbase + (c+2)*64*HDIM, (c & 1) ? FA_K1 : FA_K0);
            issue64(vbase + (c+2)*64*HDIM, (c & 1) ? FA_V1 : FA_V0);
        }
        CP_COMMIT();
    }

    float inv0 = 1.f / l0, inv1 = 1.f / l1;
    int row = lane >> 2;
    int gq0 = q0 + w*16 + row;
    #pragma unroll
    for (int j = 0; j < 8; j++) {
        int col = j*8 + (lane & 3)*2;
        *(__half2*)(Oh + ((size_t)(n*LTOK + gq0))*WDIM + h*HDIM + col) =
            __floats2half2_rn(od[j][0]*inv0, od[j][1]*inv0);
        *(__half2*)(Oh + ((size_t)(n*LTOK + gq0 + 8))*WDIM + h*HDIM + col) =
            __floats2half2_rn(od[j][2]*inv1, od[j][3]*inv1);
    }
}

// ---------------- final mean ----------------
__global__ void mean_k(const float* __restrict__ y, float* __restrict__ out) {
    int c = blockIdx.x*256 + threadIdx.x;
    int n = blockIdx.y;
    if (c >= WDIM) return;
    float acc = 0.f;
    for (int l = 0; l < LTOK; l++)
        acc += y[(size_t)(n*LTOK + l)*WDIM + c];
    out[(size_t)n*WDIM + c] = acc * (1.f/(float)LTOK);
}

// ---------------- host orchestration ----------------
extern "C" void kernel_launch(void* const* d_in, const int* in_sizes, int n_in,
                              void* d_out, int out_size) {
    const float* image     = (const float*)d_in[0];
    const float* conv_ker  = (const float*)d_in[1];
    const float* conv_bias = (const float*)d_in[2];
    const float* ln1_scale = (const float*)d_in[3];
    const float* ln1_bias  = (const float*)d_in[4];
    const float* wq        = (const float*)d_in[5];
    const float* bq        = (const float*)d_in[6];
    const float* wk        = (const float*)d_in[7];
    const float* bk        = (const float*)d_in[8];
    const float* wv        = (const float*)d_in[9];
    const float* bv        = (const float*)d_in[10];
    const float* wo        = (const float*)d_in[11];
    const float* bo        = (const float*)d_in[12];
    const float* ln2_scale = (const float*)d_in[13];
    const float* ln2_bias  = (const float*)d_in[14];
    const float* w1        = (const float*)d_in[15];
    const float* b1        = (const float*)d_in[16];
    const float* w2        = (const float*)d_in[17];
    const float* b2        = (const float*)d_in[18];
    const float* lnf_scale = (const float*)d_in[19];
    const float* lnf_bias  = (const float*)d_in[20];
    float* out = (float*)d_out;

    float *x, *y, *rope, *bqkv;
    __half *yh, *oh, *qh, *kh, *vh, *h1h, *wh, *wqkvh;
    cudaGetSymbolAddress((void**)&x,    g_x);
    cudaGetSymbolAddress((void**)&y,    g_y);
    cudaGetSymbolAddress((void**)&rope, g_rope);
    cudaGetSymbolAddress((void**)&bqkv, g_bqkv);
    cudaGetSymbolAddress((void**)&yh,   g_yh);
    cudaGetSymbolAddress((void**)&oh,   g_oh);
    cudaGetSymbolAddress((void**)&qh,   g_qh);
    cudaGetSymbolAddress((void**)&kh,   g_kh);
    cudaGetSymbolAddress((void**)&vh,   g_vh);
    cudaGetSymbolAddress((void**)&h1h,  g_h1h);
    cudaGetSymbolAddress((void**)&wh,   g_wh);
    cudaGetSymbolAddress((void**)&wqkvh,g_wqkv);

    cudaFuncSetAttribute(gemm_mma<false,false,false>, cudaFuncAttributeMaxDynamicSharedMemorySize, GEMM_SMEM);
    cudaFuncSetAttribute(gemm_mma<false,true, false>, cudaFuncAttributeMaxDynamicSharedMemorySize, GEMM_SMEM);
    cudaFuncSetAttribute(gemm_mma<true, false,true >, cudaFuncAttributeMaxDynamicSharedMemorySize, GEMM_SMEM);
    cudaFuncSetAttribute(gemm_qkv, cudaFuncAttributeMaxDynamicSharedMemorySize, GEMM_SMEM);
    cudaFuncSetAttribute(fattn_k,  cudaFuncAttributeMaxDynamicSharedMemorySize, FA_SMEM);

    __half* w_conv = wh;
    __half* w_o    = wh + (size_t)1*C0;
    __half* w_1    = wh + (size_t)5*C0;
    __half* w_2    = wh + (size_t)21*C0;

    // fused prep (one launch)
    prep_k<<<PREP_NB1 + PREP_NB2 + PREP_NB3 + PREP_NB4, 256>>>(
        conv_ker, wo, w1, w2, wq, wk, wv, bq, bk, bv, wh, wqkvh, bqkv, rope);

    im2col_k<<<(NROWS*WDIM + 255)/256, 256>>>(image, h1h);
    {
        dim3 g(WDIM/128, NROWS/64);
        gemm_mma<false,false,false><<<g, 128, GEMM_SMEM>>>(h1h, w_conv, conv_bias,
                                                           nullptr, x, nullptr,
                                                           NROWS, WDIM, WDIM);
    }

    dim3 gProj(WDIM/128,  NROWS/64);   // 6 x 72
    dim3 gQkv (QKVN/128,  NROWS/64);   // 18 x 72
    dim3 gMlp1(MLPDIM/128,NROWS/64);   // 24 x 72
    dim3 gAttn(LTOK/64, BATCH*NHEAD);  // 9 x 96
    dim3 gLn(NROWS/8);

    for (int l = 0; l < DEPTH; l++) {
        const __half* wqkv_l = wqkvh + (size_t)l*3*C0;
        const __half* wo_l   = w_o + (size_t)l*C0;
        const __half* w1_l   = w_1 + (size_t)l*4*C0;
        const __half* w2_l   = w_2 + (size_t)l*4*C0;
        const float* bqkv_l = bqkv + (size_t)l*QKVN;
        const float* bo_l = bo + (size_t)l*WDIM;
        const float* b1_l = b1 + (size_t)l*MLPDIM;
        const float* b2_l = b2 + (size_t)l*WDIM;

        ln_k<<<gLn, 256>>>(x, nullptr, yh, ln1_scale + (size_t)l*WDIM, ln1_bias + (size_t)l*WDIM);

        gemm_qkv<<<gQkv, 128, GEMM_SMEM>>>(yh, wqkv_l, bqkv_l, rope, qh, kh, vh, NROWS, QKVN, WDIM);

        fattn_k<<<gAttn, 128, FA_SMEM>>>(qh, kh, vh, oh);

        gemm_mma<false,true,false><<<gProj, 128, GEMM_SMEM>>>(oh, wo_l, bo_l, x, x, nullptr, NROWS, WDIM, WDIM);

        ln_k<<<gLn, 256>>>(x, nullptr, yh, ln2_scale + (size_t)l*WDIM, ln2_bias + (size_t)l*WDIM);

        gemm_mma<true,false,true><<<gMlp1, 128, GEMM_SMEM>>>(yh, w1_l, b1_l, nullptr, nullptr, h1h, NROWS, MLPDIM, WDIM);
        gemm_mma<false,true,false><<<gProj, 128, GEMM_SMEM>>>(h1h, w2_l, b2_l, x, x, nullptr, NROWS, WDIM, MLPDIM);
    }

    ln_k<<<gLn, 256>>>(x, y, yh, lnf_scale, lnf_bias);
    {
        dim3 g((WDIM + 255)/256, BATCH);
        mean_k<<<g, 256>>>(y, out);
    }
}

// round 14
// speedup vs baseline: 1.0472x; 1.0051x over previous
#include <cuda_runtime.h>
#include <cuda_fp16.h>
#include <cstdint>
#include <cstddef>

// ---------------- problem constants ----------------
#define BATCH   8
#define IMG     384
#define CIN     3
#define PATCH   16
#define GRIDP   24
#define LTOK    576
#define WDIM    768
#define DEPTH   4
#define NHEAD   12
#define HDIM    64
#define MLPDIM  3072
#define NROWS   (BATCH*LTOK)
#define EPS     1e-6f
#define QKVN    (3*WDIM)            // 2304
#define LOG2E   1.44269504088896f

// ---------------- PTX helpers ----------------
__device__ __forceinline__ uint32_t smem_to_u32(const void* smem_ptr) {
    uint32_t addr;
    asm("{ .reg .u64 tmp; cvta.to.shared.u64 tmp, %1; cvt.u32.u64 %0, tmp; }"
        : "=r"(addr) : "l"(smem_ptr));
    return addr;
}
__device__ __forceinline__ float ex2f(float x) {
    float r;
    asm("ex2.approx.f32 %0, %1;" : "=f"(r) : "f"(x));
    return r;
}
#define CP_ASYNC16(dst, src) \
    asm volatile("cp.async.cg.shared.global [%0], [%1], 16;" :: "r"(dst), "l"(src) : "memory")
#define CP_COMMIT() asm volatile("cp.async.commit_group;" ::: "memory")
#define CP_WAIT1()  asm volatile("cp.async.wait_group 1;" ::: "memory")

#define LDSM_X4(r, addr) \
    asm volatile("ldmatrix.sync.aligned.m8n8.x4.shared.b16 {%0,%1,%2,%3}, [%4];" \
        : "=r"((r)[0]), "=r"((r)[1]), "=r"((r)[2]), "=r"((r)[3]) : "r"(addr))
#define LDSM_X4T(r, addr) \
    asm volatile("ldmatrix.sync.aligned.m8n8.x4.trans.shared.b16 {%0,%1,%2,%3}, [%4];" \
        : "=r"((r)[0]), "=r"((r)[1]), "=r"((r)[2]), "=r"((r)[3]) : "r"(addr))

#define MMA16816(d, a, b0, b1) \
    asm volatile("mma.sync.aligned.m16n8k16.row.col.f32.f16.f16.f32 " \
        "{%0,%1,%2,%3}, {%4,%5,%6,%7}, {%8,%9}, {%0,%1,%2,%3};" \
        : "+f"((d)[0]), "+f"((d)[1]), "+f"((d)[2]), "+f"((d)[3]) \
        : "r"((a)[0]), "r"((a)[1]), "r"((a)[2]), "r"((a)[3]), "r"(b0), "r"(b1))

#define SWZA(off) ((off) ^ (((off) >> 3) & 0x70))   // 128B rows
#define SWZB(off) ((off) ^ (((off) >> 4) & 0x70))   // 256B rows

// ---------------- scratch ----------------
__device__ __align__(256) float g_x   [NROWS*WDIM];
__device__ __align__(256) float g_y   [NROWS*WDIM];
__device__ __align__(256) float g_rope[4*LTOK*16];
__device__ __align__(256) float g_bqkv[DEPTH*QKVN];

__device__ __align__(256) __half g_yh [NROWS*WDIM];
__device__ __align__(256) __half g_oh [NROWS*WDIM];
__device__ __align__(256) __half g_qh [NROWS*WDIM];
__device__ __align__(256) __half g_kh [NROWS*WDIM];
__device__ __align__(256) __half g_vh [NROWS*WDIM];
__device__ __align__(256) __half g_h1h[NROWS*MLPDIM];

#define C0 589824
__device__ __align__(256) __half g_wh  [37*C0];      // [conv][wo x4][w1 x4][w2 x4]
__device__ __align__(256) __half g_wqkv[12*C0];      // [l][768][2304]

// ---------------- small helpers ----------------
__device__ __forceinline__ float gelu_f(float x) {
    float u = 0.7978845608028654f*(x + 0.044715f*x*x*x);
    float t = __expf(2.f*u);
    float th = 1.f - __fdividef(2.f, t + 1.f);
    return 0.5f*x*(1.f + th);
}

// ---------------- fused prep: wcvt | wqkvcvt | bcat | rope_cache | im2col ----------------
#define PREP_NB1 21312u   // 37*C0/4 / 256
#define PREP_NB2 6912u    // 12*C0/4 / 256
#define PREP_NB3 36u      // DEPTH*QKVN / 256
#define PREP_NB4 36u      // LTOK*16 / 256
#define PREP_NB5 13824u   // NROWS*WDIM / 256
__global__ void prep_k(const float* __restrict__ conv, const float* __restrict__ wo,
                       const float* __restrict__ w1, const float* __restrict__ w2,
                       const float* __restrict__ wq, const float* __restrict__ wk,
                       const float* __restrict__ wv,
                       const float* __restrict__ bq, const float* __restrict__ bk,
                       const float* __restrict__ bv,
                       const float* __restrict__ image,
                       __half* __restrict__ wdst, __half* __restrict__ wqkvdst,
                       float* __restrict__ bdst, float* __restrict__ cache,
                       __half* __restrict__ imdst) {
    uint32_t b = blockIdx.x;
    if (b < PREP_NB1) {
        size_t i4 = ((size_t)b*256 + threadIdx.x) * 4;
        if (i4 >= (size_t)37*C0) return;
        const float* src; size_t off;
        if      (i4 < (size_t)C0)    { src = conv; off = i4; }
        else if (i4 < (size_t)5*C0)  { src = wo;   off = i4 - (size_t)C0; }
        else if (i4 < (size_t)21*C0) { src = w1;   off = i4 - (size_t)5*C0; }
        else                         { src = w2;   off = i4 - (size_t)21*C0; }
        float4 v = *(const float4*)(src + off);
        __half2* d = (__half2*)(wdst + i4);
        d[0] = __floats2half2_rn(v.x, v.y);
        d[1] = __floats2half2_rn(v.z, v.w);
    } else if (b < PREP_NB1 + PREP_NB2) {
        size_t i4 = ((size_t)(b - PREP_NB1)*256 + threadIdx.x) * 4;
        if (i4 >= (size_t)12*C0) return;
        size_t l  = i4 / ((size_t)WDIM*QKVN);
        size_t r  = i4 % ((size_t)WDIM*QKVN);
        size_t k  = r / QKVN;
        size_t j  = r % QKVN;
        size_t blk = j / WDIM;
        const float* src = (blk == 0) ? wq : (blk == 1) ? wk : wv;
        float4 v = *(const float4*)(src + l*(size_t)C0 + k*WDIM + (j - blk*WDIM));
        __half2* d = (__half2*)(wqkvdst + i4);
        d[0] = __floats2half2_rn(v.x, v.y);
        d[1] = __floats2half2_rn(v.z, v.w);
    } else if (b < PREP_NB1 + PREP_NB2 + PREP_NB3) {
        int idx = (int)(b - PREP_NB1 - PREP_NB2)*256 + threadIdx.x;
        if (idx >= DEPTH*QKVN) return;
        int l = idx / QKVN, j = idx % QKVN;
        int blk = j / WDIM;
        const float* src = (blk == 0) ? bq : (blk == 1) ? bk : bv;
        bdst[idx] = src[l*WDIM + (j - blk*WDIM)];
    } else if (b < PREP_NB1 + PREP_NB2 + PREP_NB3 + PREP_NB4) {
        int idx = (int)(b - PREP_NB1 - PREP_NB2 - PREP_NB3)*256 + threadIdx.x;
        if (idx >= LTOK*16) return;
        int f = idx % 16, l = idx / 16;
        float freq = (float)f / (15.f + 1e-9f);
        float inv  = powf(10000.f, -freq);
        float u = ((float)(l % GRIDP) + 0.5f) / (float)GRIDP;
        float v = ((float)(l / GRIDP) + 0.5f) / (float)GRIDP;
        float ax = u*inv, ay = v*inv;
        cache[0*LTOK*16 + idx] = cosf(ax);
        cache[1*LTOK*16 + idx] = sinf(ax);
        cache[2*LTOK*16 + idx] = cosf(ay);
        cache[3*LTOK*16 + idx] = sinf(ay);
    } else {
        int idx = (int)(b - PREP_NB1 - PREP_NB2 - PREP_NB3 - PREP_NB4)*256 + threadIdx.x;
        if (idx >= NROWS*WDIM) return;
        int t  = idx % WDIM;
        int nl = idx / WDIM;
        int l  = nl % LTOK;
        int n  = nl / LTOK;
        int ci = t % 3;
        int ij = t / 3;
        int j  = ij % PATCH;
        int i  = ij / PATCH;
        int px = l % GRIDP, py = l / GRIDP;
        float v = image[ (((size_t)n*IMG + (py*PATCH+i))*IMG + (px*PATCH+j))*CIN + ci ];
        imdst[idx] = __float2half_rn(v);
    }
}

// ---------------- layernorm: warp per row ----------------
__global__ void ln_k(const float* __restrict__ x, float* __restrict__ y,
                     __half* __restrict__ yh,
                     const float* __restrict__ sc, const float* __restrict__ bi) {
    int wid = threadIdx.x >> 5, lane = threadIdx.x & 31;
    int row = blockIdx.x*8 + wid;
    const float4* xr = (const float4*)(x + (size_t)row*WDIM);
    float4 v[6];
    float s = 0.f, sq = 0.f;
    #pragma unroll
    for (int j = 0; j < 6; j++) {
        v[j] = xr[lane + j*32];
        s  += v[j].x + v[j].y + v[j].z + v[j].w;
        sq += v[j].x*v[j].x + v[j].y*v[j].y + v[j].z*v[j].z + v[j].w*v[j].w;
    }
    #pragma unroll
    for (int o = 16; o; o >>= 1) {
        s  += __shfl_xor_sync(0xffffffffu, s,  o);
        sq += __shfl_xor_sync(0xffffffffu, sq, o);
    }
    float m   = s * (1.f/(float)WDIM);
    float var = sq * (1.f/(float)WDIM) - m*m;
    float inv = rsqrtf(var + EPS);
    size_t base = (size_t)row*WDIM;
    #pragma unroll
    for (int j = 0; j < 6; j++) {
        int c = (lane + j*32)*4;
        float4 scv = *(const float4*)(sc + c);
        float4 biv = *(const float4*)(bi + c);
        float o0 = (v[j].x - m)*inv*scv.x + biv.x;
        float o1 = (v[j].y - m)*inv*scv.y + biv.y;
        float o2 = (v[j].z - m)*inv*scv.z + biv.z;
        float o3 = (v[j].w - m)*inv*scv.w + biv.w;
        if (y) *(float4*)(y + base + c) = make_float4(o0, o1, o2, o3);
        __half2 h0 = __floats2half2_rn(o0, o1);
        __half2 h1 = __floats2half2_rn(o2, o3);
        *(uint2*)(yh + base + c) = make_uint2(*(uint32_t*)&h0, *(uint32_t*)&h1);
    }
}

// ---------------- GEMM core (tile 64x128, 128 thr, 3 stages, ONE barrier/chunk) ----------------
#define GSTAGES 3
#define STAGE_BYTES 24576
#define GEMM_SMEM (GSTAGES*STAGE_BYTES)

#define GEMM_PREAMBLE \
    extern __shared__ __align__(1024) char smem[]; \
    const uint32_t sbase = smem_to_u32(smem); \
    int tid = threadIdx.x; \
    int wid = tid >> 5, lane = tid & 31; \
    int bn = blockIdx.x * 128, bm = blockIdx.y * 64; \
    const __half* Aptr = A + (size_t)bm*K; \
    const int nch = K >> 6; \
    auto issue = [&](int ch, int stg) { \
        uint32_t sA = sbase + stg*STAGE_BYTES; \
        uint32_t sB = sA + 8192; \
        const __half* srcA = Aptr + ch*64; \
        _Pragma("unroll") \
        for (int rr = 0; rr < 4; rr++) { \
            int idx = rr*128 + tid; \
            int row = idx >> 3, u = idx & 7; \
            CP_ASYNC16(sA + SWZA((uint32_t)(row*128 + u*16)), srcA + (size_t)row*K + u*8); \
        } \
        const __half* srcB = B + (size_t)(ch*64)*N + bn; \
        _Pragma("unroll") \
        for (int rr = 0; rr < 8; rr++) { \
            int idx = rr*128 + tid; \
            int row = idx >> 4, u = idx & 15; \
            CP_ASYNC16(sB + SWZB((uint32_t)(row*256 + u*16)), srcB + (size_t)row*N + u*8); \
        } \
    }; \
    int m0w = (wid >> 1) * 32, n0w = (wid & 1) * 64; \
    int jj = lane >> 3, rr8 = lane & 7; \
    int arow = m0w + (jj & 1)*8 + rr8; \
    int acol = (jj >> 1) * 8; \
    int btrow = lane & 15; \
    int btcol = n0w + ((lane >> 4) << 3); \
    float acc[2][8][4]; \
    _Pragma("unroll") \
    for (int mt = 0; mt < 2; mt++) \
        _Pragma("unroll") \
        for (int nt = 0; nt < 8; nt++) \
            _Pragma("unroll") \
            for (int r = 0; r < 4; r++) acc[mt][nt][r] = 0.f; \
    issue(0, 0); CP_COMMIT(); \
    issue(1, 1); CP_COMMIT(); \
    for (int ch = 0; ch < nch; ch++) { \
        CP_WAIT1(); \
        __syncthreads(); \
        if (ch + 2 < nch) issue(ch + 2, (ch + 2) % GSTAGES); \
        CP_COMMIT(); \
        uint32_t sA = sbase + (ch % GSTAGES)*STAGE_BYTES; \
        uint32_t sB = sA + 8192; \
        _Pragma("unroll") \
        for (int kk = 0; kk < 4; kk++) { \
            uint32_t a[2][4]; \
            _Pragma("unroll") \
            for (int mt = 0; mt < 2; mt++) { \
                uint32_t off = (uint32_t)((arow + mt*16)*128 + (kk*16 + acol)*2); \
                LDSM_X4(a[mt], sA + SWZA(off)); \
            } \
            uint32_t bt[4][4]; \
            _Pragma("unroll") \
            for (int np = 0; np < 4; np++) { \
                uint32_t off = (uint32_t)((kk*16 + btrow)*256 + (btcol + np*16)*2); \
                LDSM_X4T(bt[np], sB + SWZB(off)); \
            } \
            _Pragma("unroll") \
            for (int mt = 0; mt < 2; mt++) \
                _Pragma("unroll") \
                for (int nt = 0; nt < 8; nt++) \
                    MMA16816(acc[mt][nt], a[mt], bt[nt>>1][(nt&1)*2], bt[nt>>1][(nt&1)*2+1]); \
        } \
    } \
    int lr = lane >> 2, lc = (lane & 3) * 2;

// ---------------- standard GEMM (fp32/fp16 out, residual, gelu) ----------------
template<bool GELU, bool RES, bool HOUT>
__global__ void __launch_bounds__(128, 3)
gemm_mma(const __half* __restrict__ A, const __half* __restrict__ B,
         const float* __restrict__ bias, const float* __restrict__ R,
         float* __restrict__ C, __half* __restrict__ Ch,
         int M, int N, int K) {
    GEMM_PREAMBLE
    #pragma unroll
    for (int mt = 0; mt < 2; mt++) {
        #pragma unroll
        for (int nt = 0; nt < 8; nt++) {
            int col = bn + n0w + nt*8 + lc;
            float b0 = bias[col], b1 = bias[col+1];
            int r0 = bm + m0w + mt*16 + lr;
            #pragma unroll
            for (int half = 0; half < 2; half++) {
                int m = r0 + half*8;
                float v0 = acc[mt][nt][half*2]   + b0;
                float v1 = acc[mt][nt][half*2+1] + b1;
                if (GELU) { v0 = gelu_f(v0); v1 = gelu_f(v1); }
                size_t o = (size_t)m*N + col;
                if (HOUT) {
                    *(__half2*)(Ch + o) = __floats2half2_rn(v0, v1);
                } else {
                    if (RES) {
                        float2 rv = *(const float2*)(R + o);
                        v0 += rv.x; v1 += rv.y;
                    }
                    *(float2*)(C + o) = make_float2(v0, v1);
                }
            }
        }
    }
}

// ---------------- QKV GEMM: rope + head-major fp16 epilogue ----------------
// Q pre-scaled by 0.125 * LOG2E so attention softmax can use raw ex2.
__global__ void __launch_bounds__(128, 3)
gemm_qkv(const __half* __restrict__ A, const __half* __restrict__ B,
         const float* __restrict__ bias, const float* __restrict__ cache,
         __half* __restrict__ Qh, __half* __restrict__ Kh, __half* __restrict__ Vh,
         int M, int N, int K) {
    GEMM_PREAMBLE
    #pragma unroll
    for (int mt = 0; mt < 2; mt++) {
        #pragma unroll
        for (int nt = 0; nt < 8; nt++) {
            int colg = bn + n0w + nt*8 + lc;
            float b0 = bias[colg], b1 = bias[colg+1];
            int plane = colg / WDIM;
            int rem   = colg - plane*WDIM;
            int hh = rem >> 6;
            int d  = rem & 63;          // even
            int p  = d >> 1;
            int r0 = bm + m0w + mt*16 + lr;
            #pragma unroll
            for (int half = 0; half < 2; half++) {
                int m = r0 + half*8;
                int n = m / LTOK, l = m - n*LTOK;
                float v0 = acc[mt][nt][half*2]   + b0;
                float v1 = acc[mt][nt][half*2+1] + b1;
                size_t dsto = ((size_t)(n*NHEAD + hh)*LTOK + l)*HDIM + d;
                if (plane == 2) {
                    *(__half2*)(Vh + dsto) = __floats2half2_rn(v0, v1);
                } else {
                    float c, s;
                    if (p < 16) { c = cache[l*16 + p];             s = cache[LTOK*16 + l*16 + p]; }
                    else        { c = cache[2*LTOK*16 + l*16 + p-16]; s = cache[3*LTOK*16 + l*16 + p-16]; }
                    float rx = v0*c - v1*s;
                    float ry = v0*s + v1*c;
                    if (plane == 0) {
                        rx *= 0.125f*LOG2E; ry *= 0.125f*LOG2E;
                        *(__half2*)(Qh + dsto) = __floats2half2_rn(rx, ry);
                    } else {
                        *(__half2*)(Kh + dsto) = __floats2half2_rn(rx, ry);
                    }
                }
            }
        }
    }
}

// ---------------- single-pass flash attention (log2-domain softmax) ----------------
#define FA_SQ   0
#define FA_K0   8192
#define FA_V0   16384
#define FA_K1   24576
#define FA_V1   32768
#define FA_SMEM 40960

__global__ void __launch_bounds__(128, 3)
fattn_k(const __half* __restrict__ Qh, const __half* __restrict__ Kh,
        const __half* __restrict__ Vh, __half* __restrict__ Oh) {
    extern __shared__ __align__(1024) char smem[];
    const uint32_t sb = smem_to_u32(smem);
    int tid = threadIdx.x;
    int w = tid >> 5, lane = tid & 31;
    int q0 = blockIdx.x * 64;
    int nh = blockIdx.y;
    int h  = nh % NHEAD, n = nh / NHEAD;

    const __half* qbase = Qh + ((size_t)nh*LTOK + q0)*HDIM;
    const __half* kbase = Kh + (size_t)nh*LTOK*HDIM;
    const __half* vbase = Vh + (size_t)nh*LTOK*HDIM;

    auto issue64 = [&](const __half* src, uint32_t dstoff) {
        #pragma unroll
        for (int it = 0; it < 4; it++) {
            int idx = it*128 + tid;
            int row = idx >> 3, u = idx & 7;
            CP_ASYNC16(sb + dstoff + SWZA((uint32_t)(row*128 + u*16)), src + row*HDIM + u*8);
        }
    };

    issue64(qbase, FA_SQ);
    issue64(kbase, FA_K0);
    issue64(vbase, FA_V0);
    CP_COMMIT();
    issue64(kbase + 64*HDIM, FA_K1);
    issue64(vbase + 64*HDIM, FA_V1);
    CP_COMMIT();

    float m0 = -1e30f, m1 = -1e30f, l0 = 0.f, l1 = 0.f;
    float od[8][4];
    #pragma unroll
    for (int j = 0; j < 8; j++)
        #pragma unroll
        for (int r = 0; r < 4; r++) od[j][r] = 0.f;
    uint32_t qf[4][4];

    const int NCH = LTOK / 64;   // 9
    for (int c = 0; c < NCH; c++) {
        CP_WAIT1();
        __syncthreads();
        uint32_t kbuf = (c & 1) ? FA_K1 : FA_K0;
        uint32_t vbuf = (c & 1) ? FA_V1 : FA_V0;
        if (c == 0) {
            #pragma unroll
            for (int kk = 0; kk < 4; kk++) {
                uint32_t off = (uint32_t)((w*16 + (lane & 15))*128 + (kk*16 + ((lane>>4)<<3))*2);
                LDSM_X4(qf[kk], sb + FA_SQ + SWZA(off));
            }
        }
        float sf[8][4];
        #pragma unroll
        for (int j = 0; j < 8; j++)
            #pragma unroll
            for (int r = 0; r < 4; r++) sf[j][r] = 0.f;
        #pragma unroll
        for (int kk = 0; kk < 4; kk++) {
            #pragma unroll
            for (int kt = 0; kt < 4; kt++) {
                uint32_t bf[4];
                uint32_t off = (uint32_t)((kt*16 + (lane & 15))*128 + (kk*16 + ((lane>>4)<<3))*2);
                LDSM_X4(bf, sb + kbuf + SWZA(off));
                MMA16816(sf[2*kt],   qf[kk], bf[0], bf[2]);
                MMA16816(sf[2*kt+1], qf[kk], bf[1], bf[3]);
            }
        }
        float cm0 = -1e30f, cm1 = -1e30f;
        #pragma unroll
        for (int j = 0; j < 8; j++) {
            cm0 = fmaxf(cm0, fmaxf(sf[j][0], sf[j][1]));
            cm1 = fmaxf(cm1, fmaxf(sf[j][2], sf[j][3]));
        }
        cm0 = fmaxf(cm0, __shfl_xor_sync(0xffffffffu, cm0, 1));
        cm0 = fmaxf(cm0, __shfl_xor_sync(0xffffffffu, cm0, 2));
        cm1 = fmaxf(cm1, __shfl_xor_sync(0xffffffffu, cm1, 1));
        cm1 = fmaxf(cm1, __shfl_xor_sync(0xffffffffu, cm1, 2));
        float nm0 = fmaxf(m0, cm0), nm1 = fmaxf(m1, cm1);
        float sc0 = ex2f(m0 - nm0), sc1 = ex2f(m1 - nm1);
        m0 = nm0; m1 = nm1;
        float rs0 = 0.f, rs1 = 0.f;
        uint32_t pa[4][4];
        #pragma unroll
        for (int t = 0; t < 4; t++) {
            float e00 = ex2f(sf[2*t][0]   - m0), e01 = ex2f(sf[2*t][1]   - m0);
            float e10 = ex2f(sf[2*t][2]   - m1), e11 = ex2f(sf[2*t][3]   - m1);
            float e20 = ex2f(sf[2*t+1][0] - m0), e21 = ex2f(sf[2*t+1][1] - m0);
            float e30 = ex2f(sf[2*t+1][2] - m1), e31 = ex2f(sf[2*t+1][3] - m1);
            rs0 += e00 + e01 + e20 + e21;
            rs1 += e10 + e11 + e30 + e31;
            __half2 h;
            h = __floats2half2_rn(e00, e01); pa[t][0] = *(uint32_t*)&h;
            h = __floats2half2_rn(e10, e11); pa[t][1] = *(uint32_t*)&h;
            h = __floats2half2_rn(e20, e21); pa[t][2] = *(uint32_t*)&h;
            h = __floats2half2_rn(e30, e31); pa[t][3] = *(uint32_t*)&h;
        }
        rs0 += __shfl_xor_sync(0xffffffffu, rs0, 1);
        rs0 += __shfl_xor_sync(0xffffffffu, rs0, 2);
        rs1 += __shfl_xor_sync(0xffffffffu, rs1, 1);
        rs1 += __shfl_xor_sync(0xffffffffu, rs1, 2);
        l0 = l0*sc0 + rs0;
        l1 = l1*sc1 + rs1;
        #pragma unroll
        for (int j = 0; j < 8; j++) {
            od[j][0] *= sc0; od[j][1] *= sc0;
            od[j][2] *= sc1; od[j][3] *= sc1;
        }
        #pragma unroll
        for (int t = 0; t < 4; t++) {
            #pragma unroll
            for (int dt = 0; dt < 4; dt++) {
                uint32_t vb[4];
                uint32_t off = (uint32_t)((t*16 + (lane & 15))*128 + (dt*16 + ((lane>>4)<<3))*2);
                LDSM_X4T(vb, sb + vbuf + SWZA(off));
                MMA16816(od[2*dt],   pa[t], vb[0], vb[1]);
                MMA16816(od[2*dt+1], pa[t], vb[2], vb[3]);
            }
        }
        __syncthreads();
        if (c + 2 < NCH) {
            issue64(kbase + (c+2)*64*HDIM, (c & 1) ? FA_K1 : FA_K0);
            issue64(vbase + (c+2)*64*HDIM, (c & 1) ? FA_V1 : FA_V0);
        }
        CP_COMMIT();
    }

    float inv0 = 1.f / l0, inv1 = 1.f / l1;
    int row = lane >> 2;
    int gq0 = q0 + w*16 + row;
    #pragma unroll
    for (int j = 0; j < 8; j++) {
        int col = j*8 + (lane & 3)*2;
        *(__half2*)(Oh + ((size_t)(n*LTOK + gq0))*WDIM + h*HDIM + col) =
            __floats2half2_rn(od[j][0]*inv0, od[j][1]*inv0);
        *(__half2*)(Oh + ((size_t)(n*LTOK + gq0 + 8))*WDIM + h*HDIM + col) =
            __floats2half2_rn(od[j][2]*inv1, od[j][3]*inv1);
    }
}

// ---------------- final mean ----------------
__global__ void mean_k(const float* __restrict__ y, float* __restrict__ out) {
    int c = blockIdx.x*256 + threadIdx.x;
    int n = blockIdx.y;
    if (c >= WDIM) return;
    float acc = 0.f;
    for (int l = 0; l < LTOK; l++)
        acc += y[(size_t)(n*LTOK + l)*WDIM + c];
    out[(size_t)n*WDIM + c] = acc * (1.f/(float)LTOK);
}

// ---------------- host orchestration ----------------
extern "C" void kernel_launch(void* const* d_in, const int* in_sizes, int n_in,
                              void* d_out, int out_size) {
    const float* image     = (const float*)d_in[0];
    const float* conv_ker  = (const float*)d_in[1];
    const float* conv_bias = (const float*)d_in[2];
    const float* ln1_scale = (const float*)d_in[3];
    const float* ln1_bias  = (const float*)d_in[4];
    const float* wq        = (const float*)d_in[5];
    const float* bq        = (const float*)d_in[6];
    const float* wk        = (const float*)d_in[7];
    const float* bk        = (const float*)d_in[8];
    const float* wv        = (const float*)d_in[9];
    const float* bv        = (const float*)d_in[10];
    const float* wo        = (const float*)d_in[11];
    const float* bo        = (const float*)d_in[12];
    const float* ln2_scale = (const float*)d_in[13];
    const float* ln2_bias  = (const float*)d_in[14];
    const float* w1        = (const float*)d_in[15];
    const float* b1        = (const float*)d_in[16];
    const float* w2        = (const float*)d_in[17];
    const float* b2        = (const float*)d_in[18];
    const float* lnf_scale = (const float*)d_in[19];
    const float* lnf_bias  = (const float*)d_in[20];
    float* out = (float*)d_out;

    float *x, *y, *rope, *bqkv;
    __half *yh, *oh, *qh, *kh, *vh, *h1h, *wh, *wqkvh;
    cudaGetSymbolAddress((void**)&x,    g_x);
    cudaGetSymbolAddress((void**)&y,    g_y);
    cudaGetSymbolAddress((void**)&rope, g_rope);
    cudaGetSymbolAddress((void**)&bqkv, g_bqkv);
    cudaGetSymbolAddress((void**)&yh,   g_yh);
    cudaGetSymbolAddress((void**)&oh,   g_oh);
    cudaGetSymbolAddress((void**)&qh,   g_qh);
    cudaGetSymbolAddress((void**)&kh,   g_kh);
    cudaGetSymbolAddress((void**)&vh,   g_vh);
    cudaGetSymbolAddress((void**)&h1h,  g_h1h);
    cudaGetSymbolAddress((void**)&wh,   g_wh);
    cudaGetSymbolAddress((void**)&wqkvh,g_wqkv);

    cudaFuncSetAttribute(gemm_mma<false,false,false>, cudaFuncAttributeMaxDynamicSharedMemorySize, GEMM_SMEM);
    cudaFuncSetAttribute(gemm_mma<false,true, false>, cudaFuncAttributeMaxDynamicSharedMemorySize, GEMM_SMEM);
    cudaFuncSetAttribute(gemm_mma<true, false,true >, cudaFuncAttributeMaxDynamicSharedMemorySize, GEMM_SMEM);
    cudaFuncSetAttribute(gemm_qkv, cudaFuncAttributeMaxDynamicSharedMemorySize, GEMM_SMEM);
    cudaFuncSetAttribute(fattn_k,  cudaFuncAttributeMaxDynamicSharedMemorySize, FA_SMEM);

    __half* w_conv = wh;
    __half* w_o    = wh + (size_t)1*C0;
    __half* w_1    = wh + (size_t)5*C0;
    __half* w_2    = wh + (size_t)21*C0;

    // fused prep + im2col (one launch)
    prep_k<<<PREP_NB1 + PREP_NB2 + PREP_NB3 + PREP_NB4 + PREP_NB5, 256>>>(
        conv_ker, wo, w1, w2, wq, wk, wv, bq, bk, bv, image,
        wh, wqkvh, bqkv, rope, h1h);

    {   // embed GEMM
        dim3 g(WDIM/128, NROWS/64);
        gemm_mma<false,false,false><<<g, 128, GEMM_SMEM>>>(h1h, w_conv, conv_bias,
                                                           nullptr, x, nullptr,
                                                           NROWS, WDIM, WDIM);
    }

    dim3 gProj(WDIM/128,  NROWS/64);   // 6 x 72
    dim3 gQkv (QKVN/128,  NROWS/64);   // 18 x 72
    dim3 gMlp1(MLPDIM/128,NROWS/64);   // 24 x 72
    dim3 gAttn(LTOK/64, BATCH*NHEAD);  // 9 x 96
    dim3 gLn(NROWS/8);

    for (int l = 0; l < DEPTH; l++) {
        const __half* wqkv_l = wqkvh + (size_t)l*3*C0;
        const __half* wo_l   = w_o + (size_t)l*C0;
        const __half* w1_l   = w_1 + (size_t)l*4*C0;
        const __half* w2_l   = w_2 + (size_t)l*4*C0;
        const float* bqkv_l = bqkv + (size_t)l*QKVN;
        const float* bo_l = bo + (size_t)l*WDIM;
        const float* b1_l = b1 + (size_t)l*MLPDIM;
        const float* b2_l = b2 + (size_t)l*WDIM;

        ln_k<<<gLn, 256>>>(x, nullptr, yh, ln1_scale + (size_t)l*WDIM, ln1_bias + (size_t)l*WDIM);

        gemm_qkv<<<gQkv, 128, GEMM_SMEM>>>(yh, wqkv_l, bqkv_l, rope, qh, kh, vh, NROWS, QKVN, WDIM);

        fattn_k<<<gAttn, 128, FA_SMEM>>>(qh, kh, vh, oh);

        gemm_mma<false,true,false><<<gProj, 128, GEMM_SMEM>>>(oh, wo_l, bo_l, x, x, nullptr, NROWS, WDIM, WDIM);

        ln_k<<<gLn, 256>>>(x, nullptr, yh, ln2_scale + (size_t)l*WDIM, ln2_bias + (size_t)l*WDIM);

        gemm_mma<true,false,true><<<gMlp1, 128, GEMM_SMEM>>>(yh, w1_l, b1_l, nullptr, nullptr, h1h, NROWS, MLPDIM, WDIM);
        gemm_mma<false,true,false><<<gProj, 128, GEMM_SMEM>>>(h1h, w2_l, b2_l, x, x, nullptr, NROWS, WDIM, MLPDIM);
    }

    ln_k<<<gLn, 256>>>(x, y, yh, lnf_scale, lnf_bias);
    {
        dim3 g((WDIM + 255)/256, BATCH);
        mean_k<<<g, 256>>>(y, out);
    }
}